// round 10
// baseline (speedup 1.0000x reference)
#include <cuda_runtime.h>
#include <cstdint>

typedef unsigned long long ull;

#define B_   4
#define S_   2048
#define DM_  2048
#define DS_  64
#define REC_ 336   // q[0:64] k[64:128] a[128:192] km[192:256] v[256:320] g,h,c,g2[320:324] pad->336

// ---------------- f32x2 packed helpers ----------------
__device__ __forceinline__ ull fma2(ull a, ull b, ull c) {
    ull d; asm("fma.rn.f32x2 %0,%1,%2,%3;" : "=l"(d) : "l"(a), "l"(b), "l"(c)); return d;
}
__device__ __forceinline__ ull mul2(ull a, ull b) {
    ull d; asm("mul.rn.f32x2 %0,%1,%2;" : "=l"(d) : "l"(a), "l"(b)); return d;
}
__device__ __forceinline__ ull pack2(float lo, float hi) {
    ull d; asm("mov.b64 %0, {%1,%2};" : "=l"(d) : "f"(lo), "f"(hi)); return d;
}
__device__ __forceinline__ float2 unpack2(ull a) {
    float lo, hi; asm("mov.b64 {%0,%1}, %2;" : "=f"(lo), "=f"(hi) : "l"(a));
    return make_float2(lo, hi);
}

// ---------------- cp.async ----------------
__device__ __forceinline__ void cp_async16(void* smem, const void* gmem) {
    uint32_t s = (uint32_t)__cvta_generic_to_shared(smem);
    asm volatile("cp.async.cg.shared.global [%0], [%1], 16;" :: "r"(s), "l"(gmem) : "memory");
}
#define CP_COMMIT()  asm volatile("cp.async.commit_group;" ::: "memory")
#define CP_WAIT3()   asm volatile("cp.async.wait_group 3;" ::: "memory")
#define BAR0()       asm volatile("bar.sync 0;" ::: "memory")

// ---------------- scratch ----------------
__device__ float g_raw[B_ * S_ * 256];
__device__ float g_inp[B_ * S_ * REC_];
__device__ float g_y  [B_ * S_ * DS_];

// =====================================================================
// Kernel A: projection GEMM (proven)
// =====================================================================
#define BM 64
#define BN 64
#define BK 32

__global__ void __launch_bounds__(256) proj_gemm(
    const float* __restrict__ x,
    const float* __restrict__ Wk, const float* __restrict__ Wv,
    const float* __restrict__ Wq, const float* __restrict__ Wa)
{
    __shared__ __align__(16) float As[BK][BM + 4];
    __shared__ __align__(16) float Bs[BK][BN + 4];

    const int mt = blockIdx.x;
    const int nt = blockIdx.y;
    const float* W = (nt == 0) ? Wk : (nt == 1) ? Wv : (nt == 2) ? Wq : Wa;

    const int tid  = threadIdx.x;
    const int lrow = tid >> 2;
    const int lk   = (tid & 3) * 4;
    const float* xg = x + (size_t)(mt * BM + lrow) * DM_ + lk;
    const float* wg = W + (size_t)lrow * DM_ + lk;

    const int tn4 = (tid & 15) * 4;
    const int tm4 = (tid >> 4) * 4;

    ull acc[4][2];
    #pragma unroll
    for (int i = 0; i < 4; i++) { acc[i][0] = 0ull; acc[i][1] = 0ull; }

    float4 av0 = *(const float4*)xg;
    float4 av1 = *(const float4*)(xg + 16);
    float4 bv0 = *(const float4*)wg;
    float4 bv1 = *(const float4*)(wg + 16);

    for (int k0 = 0; k0 < DM_; k0 += BK) {
        __syncthreads();
        As[lk + 0][lrow] = av0.x; As[lk + 1][lrow] = av0.y;
        As[lk + 2][lrow] = av0.z; As[lk + 3][lrow] = av0.w;
        As[lk + 16][lrow] = av1.x; As[lk + 17][lrow] = av1.y;
        As[lk + 18][lrow] = av1.z; As[lk + 19][lrow] = av1.w;
        Bs[lk + 0][lrow] = bv0.x; Bs[lk + 1][lrow] = bv0.y;
        Bs[lk + 2][lrow] = bv0.z; Bs[lk + 3][lrow] = bv0.w;
        Bs[lk + 16][lrow] = bv1.x; Bs[lk + 17][lrow] = bv1.y;
        Bs[lk + 18][lrow] = bv1.z; Bs[lk + 19][lrow] = bv1.w;
        if (k0 + BK < DM_) {
            av0 = *(const float4*)(xg + k0 + BK);
            av1 = *(const float4*)(xg + k0 + BK + 16);
            bv0 = *(const float4*)(wg + k0 + BK);
            bv1 = *(const float4*)(wg + k0 + BK + 16);
        }
        __syncthreads();
        #pragma unroll
        for (int kk = 0; kk < BK; kk++) {
            ulonglong2 bb = *(const ulonglong2*)&Bs[kk][tn4];
            float4 a4 = *(const float4*)&As[kk][tm4];
            ull p0 = pack2(a4.x, a4.x), p1 = pack2(a4.y, a4.y);
            ull p2 = pack2(a4.z, a4.z), p3 = pack2(a4.w, a4.w);
            acc[0][0] = fma2(p0, bb.x, acc[0][0]); acc[0][1] = fma2(p0, bb.y, acc[0][1]);
            acc[1][0] = fma2(p1, bb.x, acc[1][0]); acc[1][1] = fma2(p1, bb.y, acc[1][1]);
            acc[2][0] = fma2(p2, bb.x, acc[2][0]); acc[2][1] = fma2(p2, bb.y, acc[2][1]);
            acc[3][0] = fma2(p3, bb.x, acc[3][0]); acc[3][1] = fma2(p3, bb.y, acc[3][1]);
        }
    }

    #pragma unroll
    for (int i = 0; i < 4; i++) {
        int m = mt * BM + tm4 + i;
        #pragma unroll
        for (int j = 0; j < 2; j++) {
            float2 f = unpack2(acc[i][j]);
            *(float2*)&g_raw[(size_t)m * 256 + nt * 64 + tn4 + 2 * j] = f;
        }
    }
}

// =====================================================================
// Kernel B: per-token prep (proven)
// =====================================================================
__global__ void __launch_bounds__(256) prep_kernel(
    const float* __restrict__ Wa_b, const float* __restrict__ lam)
{
    const int g    = blockIdx.x * 8 + (threadIdx.x >> 5);
    const int lane = threadIdx.x & 31;
    const float* r_ = g_raw + (size_t)g * 256;

    float k0 = r_[lane],        k1 = r_[lane + 32];
    float v0 = r_[64 + lane],   v1 = r_[96 + lane];
    float q0 = r_[128 + lane],  q1 = r_[160 + lane];
    float z0 = r_[192 + lane] + Wa_b[lane];
    float z1 = r_[224 + lane] + Wa_b[lane + 32];

    float kn = k0 * k0 + k1 * k1;
    #pragma unroll
    for (int m = 1; m < 32; m <<= 1) kn += __shfl_xor_sync(~0u, kn, m);
    float kinv = 1.0f / fmaxf(sqrtf(kn), 1e-12f);
    k0 *= kinv; k1 *= kinv;

    float qn = q0 * q0 + q1 * q1;
    #pragma unroll
    for (int m = 1; m < 32; m <<= 1) qn += __shfl_xor_sync(~0u, qn, m);
    float qinv = 1.0f / fmaxf(sqrtf(qn), 1e-12f);
    q0 *= qinv; q1 *= qinv;

    float la0 = logf(1.0f / (1.0f + expf(-lam[lane])) + 1e-8f);
    float la1 = logf(1.0f / (1.0f + expf(-lam[lane + 32])) + 1e-8f);
    float rr0 = 1.0f / (1.0f + expf(-z0));
    float rr1 = 1.0f / (1.0f + expf(-z1));
    float al0 = expf(8.0f * rr0 * la0);
    float al1 = expf(8.0f * rr1 * la1);
    float km0 = k0 * (1.0f - al0), km1 = k1 * (1.0f - al1);

    float c = q0 * km0 + q1 * km1;
    #pragma unroll
    for (int m = 1; m < 32; m <<= 1) c += __shfl_xor_sync(~0u, c, m);

    float* o = g_inp + (size_t)g * REC_;
    o[lane] = q0;          o[lane + 32] = q1;
    o[64 + lane] = k0;     o[96 + lane] = k1;
    o[128 + lane] = al0;   o[160 + lane] = al1;
    o[192 + lane] = km0;   o[224 + lane] = km1;
    o[256 + lane] = v0;    o[288 + lane] = v1;
    if (lane == 0) o[322] = c;
}

// =====================================================================
// Kernel B2: scalars vs km_{t-1}: g = q.km', h = k.km', g2 = (q.a).km'
// =====================================================================
__global__ void __launch_bounds__(256) ghc_kernel()
{
    const int g    = blockIdx.x * 8 + (threadIdx.x >> 5);
    const int lane = threadIdx.x & 31;
    const int t    = g & (S_ - 1);
    float* cur = g_inp + (size_t)g * REC_;

    float m0 = 0.0f, m1 = 0.0f;
    if (t > 0) {
        const float* prev = cur - REC_;
        m0 = prev[192 + lane]; m1 = prev[224 + lane];
    }
    float q0 = cur[lane],        q1 = cur[lane + 32];
    float k0 = cur[64 + lane],   k1 = cur[96 + lane];
    float a0 = cur[128 + lane],  a1 = cur[160 + lane];

    float gq = q0 * m0 + q1 * m1;
    float gh = k0 * m0 + k1 * m1;
    float g2 = q0 * a0 * m0 + q1 * a1 * m1;
    #pragma unroll
    for (int m = 1; m < 32; m <<= 1) {
        gq += __shfl_xor_sync(~0u, gq, m);
        gh += __shfl_xor_sync(~0u, gh, m);
        g2 += __shfl_xor_sync(~0u, g2, m);
    }
    if (lane == 0) { cur[320] = gq; cur[321] = gh; cur[323] = g2; }
}

// =====================================================================
// Kernel C: warp-specialized scan. 4 CTAs x 576 threads.
// Warps 0-15: vector (1 v x 8 k per thread). Warp 16: sequencer.
// Warp 17: dedicated cp.async loader. One bar.sync 0 per step.
// =====================================================================
__device__ __forceinline__ void ld4(ull* d, const float* p) {
    ulonglong2 t0 = *(const ulonglong2*)(p);
    ulonglong2 t1 = *(const ulonglong2*)(p + 4);
    d[0] = t0.x; d[1] = t0.y; d[2] = t1.x; d[3] = t1.y;
}

__global__ void __launch_bounds__(576, 1) scan_kernel()
{
    __shared__ __align__(16) float  stage[8][REC_];
    __shared__ __align__(16) float4 part[2][64 * 9];   // [buf][v*9 + kg], stride-9 pad
    __shared__ __align__(16) float2 swbuf[2][64];      // (sw, sw) per v

    const int b   = blockIdx.x;
    const int tid = threadIdx.x;
    const float* base = g_inp + (size_t)b * S_ * REC_;
    float* yb = g_y + (size_t)b * S_ * DS_;

    if (tid < 64) swbuf[0][tid] = make_float2(0.0f, 0.0f);
    for (int i = tid; i < 64 * 9; i += 576)
        part[0][i] = make_float4(0.f, 0.f, 0.f, 0.f);

    #pragma unroll
    for (int t = 0; t < 6; t++) {
        if (tid < 84) cp_async16(&stage[t][tid * 4], base + (size_t)t * REC_ + tid * 4);
        CP_COMMIT();
    }
    CP_WAIT3();          // records 0..2 ready
    __syncthreads();

    if (tid < 512) {
        // ===== vector warps: 1 v x 8 k per thread =====
        const int v  = tid >> 3;
        const int kg = tid & 7;
        const int ko = kg * 8;

        ull Ha[4], ac[4], kmp[4];
        ld4(ac, stage[0] + 128 + ko);      // a_0
        #pragma unroll
        for (int j = 0; j < 4; j++) { Ha[j] = 0ull; kmp[j] = 0ull; }

        for (int i = 0; i < S_; i++) {
            const float* rc = stage[i & 7];
            const float* rn = stage[(i + 1) & 7];

            ull sw2 = *(const ull*)&swbuf[i & 1][v];

            // Ha_i = a_i (.) (Ha_{i-1} + sw_i * km_{i-1})
            #pragma unroll
            for (int j = 0; j < 4; j++)
                Ha[j] = mul2(ac[j], fma2(kmp[j], sw2, Ha[j]));

            ull kmn[4], qn[4], knn[4], an[4];
            ld4(kmn, rc + 192 + ko);
            ld4(qn,  rn + ko);
            ld4(knn, rn + 64 + ko);
            ld4(an,  rn + 128 + ko);

            // dots vs Ha_i: A = q_{i+1}., C = k_{i+1}., Y = (q a)_{i+1}.
            ull qa0 = mul2(qn[0], an[0]), qa1 = mul2(qn[1], an[1]);
            ull qa2 = mul2(qn[2], an[2]), qa3 = mul2(qn[3], an[3]);
            ull A = mul2(qn[0], Ha[0]);
            ull C = mul2(knn[0], Ha[0]);
            ull Y = mul2(qa0, Ha[0]);
            A = fma2(qn[1], Ha[1], A);  C = fma2(knn[1], Ha[1], C);  Y = fma2(qa1, Ha[1], Y);
            A = fma2(qn[2], Ha[2], A);  C = fma2(knn[2], Ha[2], C);  Y = fma2(qa2, Ha[2], Y);
            A = fma2(qn[3], Ha[3], A);  C = fma2(knn[3], Ha[3], C);  Y = fma2(qa3, Ha[3], Y);

            float2 fa = unpack2(A), fc = unpack2(C), fy = unpack2(Y);
            part[(i + 1) & 1][v * 9 + kg] =
                make_float4(fa.x + fa.y, fc.x + fc.y, fy.x + fy.y, 0.0f);

            #pragma unroll
            for (int j = 0; j < 4; j++) { ac[j] = an[j]; kmp[j] = kmn[j]; }

            BAR0();
        }
    } else if (tid < 544) {
        // ===== sequencer warp =====
        const int lane = tid - 512;
        float w0 = 0.0f, w1 = 0.0f, sprev = 0.0f;

        for (int i = 0; i < S_; i++) {
            const float* rc = stage[i & 7];
            const float4* pp = part[i & 1];

            float4 x0 = pp[lane * 9 + 0], x1 = pp[lane * 9 + 1];
            float4 x2 = pp[lane * 9 + 2], x3 = pp[lane * 9 + 3];
            float4 x4 = pp[lane * 9 + 4], x5 = pp[lane * 9 + 5];
            float4 x6 = pp[lane * 9 + 6], x7 = pp[lane * 9 + 7];
            float4 z0 = pp[(lane + 32) * 9 + 0], z1 = pp[(lane + 32) * 9 + 1];
            float4 z2 = pp[(lane + 32) * 9 + 2], z3 = pp[(lane + 32) * 9 + 3];
            float4 z4 = pp[(lane + 32) * 9 + 4], z5 = pp[(lane + 32) * 9 + 5];
            float4 z6 = pp[(lane + 32) * 9 + 6], z7 = pp[(lane + 32) * 9 + 7];

            float A0 = ((x0.x + x1.x) + (x2.x + x3.x)) + ((x4.x + x5.x) + (x6.x + x7.x));
            float C0 = ((x0.y + x1.y) + (x2.y + x3.y)) + ((x4.y + x5.y) + (x6.y + x7.y));
            float Y0 = ((x0.z + x1.z) + (x2.z + x3.z)) + ((x4.z + x5.z) + (x6.z + x7.z));
            float A1 = ((z0.x + z1.x) + (z2.x + z3.x)) + ((z4.x + z5.x) + (z6.x + z7.x));
            float C1 = ((z0.y + z1.y) + (z2.y + z3.y)) + ((z4.y + z5.y) + (z6.y + z7.y));
            float Y1 = ((z0.z + z1.z) + (z2.z + z3.z)) + ((z4.z + z5.z) + (z6.z + z7.z));

            float v0 = rc[256 + lane], v1 = rc[288 + lane];
            float4 sc = *(const float4*)&rc[320];   // g, h, c, g2

            float sg = sprev * sc.x;
            float sh = sprev * sc.y;
            float u0 = v0 - A0 - sg * w0;
            float u1 = v1 - A1 - sg * w1;
            float e = u0 * u0 + u1 * u1;
            e += __shfl_xor_sync(~0u, e, 1);
            e += __shfl_xor_sync(~0u, e, 2);
            e += __shfl_xor_sync(~0u, e, 4);
            e += __shfl_xor_sync(~0u, e, 8);
            e += __shfl_xor_sync(~0u, e, 16);
            float s;
            asm("tanh.approx.f32 %0, %1;" : "=f"(s) : "f"(e * 0.499999495f));
            s = fmaf(0.5f, s, 0.5f);

            float t20 = sprev * sc.w * w0;
            float t21 = sprev * sc.w * w1;
            w0 = (v0 - C0) - sh * w0;
            w1 = (v1 - C1) - sh * w1;
            float sw0 = s * w0, sw1 = s * w1;
            swbuf[(i + 1) & 1][lane]      = make_float2(sw0, sw0);
            swbuf[(i + 1) & 1][lane + 32] = make_float2(sw1, sw1);

            yb[(size_t)i * DS_ + lane]      = Y0 + t20 + s * sc.z * w0;
            yb[(size_t)i * DS_ + lane + 32] = Y1 + t21 + s * sc.z * w1;

            sprev = s;
            BAR0();
        }
    } else {
        // ===== loader warp: cp.async 6 records ahead =====
        const int ll = tid - 544;
        for (int i = 0; i < S_; i++) {
            if (i + 6 < S_ && ll < 28) {
                const float* src = base + (size_t)(i + 6) * REC_;
                float* dst = stage[(i + 6) & 7];
                cp_async16(&dst[ll * 4],        src + ll * 4);
                cp_async16(&dst[(ll + 28) * 4], src + (ll + 28) * 4);
                cp_async16(&dst[(ll + 56) * 4], src + (ll + 56) * 4);
            }
            CP_COMMIT();
            CP_WAIT3();
            BAR0();
        }
    }
}

// =====================================================================
// Kernel D: RMS-norm(y)*norm_w @ Wo^T -> out (proven)
// =====================================================================
__global__ void __launch_bounds__(256) out_gemm(
    const float* __restrict__ norm_w, const float* __restrict__ Wo,
    float* __restrict__ out)
{
    __shared__ __align__(16) float ys[32 * 64];
    __shared__ __align__(16) float wos[64 * 128];
    __shared__ float rs[32];
    __shared__ float nws[64];

    const int tid = threadIdx.x;
    const int m0 = blockIdx.y * 32;
    const int n0 = blockIdx.x * 128;

    for (int i = tid * 4; i < 2048; i += 1024)
        *(float4*)&ys[i] = *(const float4*)&g_y[(size_t)m0 * 64 + i];
    if (tid < 64) nws[tid] = norm_w[tid];
    {
        int n  = tid & 127;
        int vb = tid >> 7;
        #pragma unroll
        for (int q = 0; q < 8; q++) {
            int v4 = vb * 8 + q;
            float4 w = *(const float4*)&Wo[(size_t)(n0 + n) * 64 + v4 * 4];
            wos[(v4 * 4 + 0) * 128 + n] = w.x;
            wos[(v4 * 4 + 1) * 128 + n] = w.y;
            wos[(v4 * 4 + 2) * 128 + n] = w.z;
            wos[(v4 * 4 + 3) * 128 + n] = w.w;
        }
    }
    __syncthreads();

    {
        int r = tid >> 3, p = tid & 7;
        float sum = 0.0f;
        #pragma unroll
        for (int j = 0; j < 8; j++) { float x = ys[r * 64 + p * 8 + j]; sum += x * x; }
        sum += __shfl_xor_sync(~0u, sum, 1);
        sum += __shfl_xor_sync(~0u, sum, 2);
        sum += __shfl_xor_sync(~0u, sum, 4);
        if (p == 0) rs[r] = rsqrtf(sum * (1.0f / 64.0f) + 1e-6f);
    }
    __syncthreads();
    for (int i = tid; i < 2048; i += 256)
        ys[i] = ys[i] * rs[i >> 6] * nws[i & 63];
    __syncthreads();

    const int tn = tid & 31;
    const int tm = tid >> 5;
    float acc[4][4];
    #pragma unroll
    for (int i = 0; i < 4; i++)
        #pragma unroll
        for (int j = 0; j < 4; j++) acc[i][j] = 0.0f;

    #pragma unroll 8
    for (int vv = 0; vv < 64; vv++) {
        float b0 = wos[vv * 128 + tn];
        float b1 = wos[vv * 128 + tn + 32];
        float b2 = wos[vv * 128 + tn + 64];
        float b3 = wos[vv * 128 + tn + 96];
        #pragma unroll
        for (int i = 0; i < 4; i++) {
            float a = ys[(tm * 4 + i) * 64 + vv];
            acc[i][0] += a * b0; acc[i][1] += a * b1;
            acc[i][2] += a * b2; acc[i][3] += a * b3;
        }
    }
    #pragma unroll
    for (int i = 0; i < 4; i++) {
        size_t row = (size_t)(m0 + tm * 4 + i) * 2048 + n0 + tn;
        #pragma unroll
        for (int j = 0; j < 4; j++) out[row + 32 * j] = acc[i][j];
    }
}

// =====================================================================
extern "C" void kernel_launch(void* const* d_in, const int* in_sizes, int n_in,
                              void* d_out, int out_size)
{
    const float* x      = (const float*)d_in[0];
    const float* Wk     = (const float*)d_in[1];
    const float* Wv     = (const float*)d_in[2];
    const float* Wq     = (const float*)d_in[3];
    const float* Wa_w   = (const float*)d_in[4];
    const float* Wa_b   = (const float*)d_in[5];
    const float* lam    = (const float*)d_in[6];
    const float* norm_w = (const float*)d_in[7];
    const float* Wo     = (const float*)d_in[8];
    float* out = (float*)d_out;

    proj_gemm<<<dim3(128, 4), 256>>>(x, Wk, Wv, Wq, Wa_w);
    prep_kernel<<<1024, 256>>>(Wa_b, lam);
    ghc_kernel<<<1024, 256>>>();
    scan_kernel<<<4, 576>>>();
    out_gemm<<<dim3(16, 256), 256>>>(norm_w, Wo, out);
}

// round 11
// speedup vs baseline: 1.2577x; 1.2577x over previous
#include <cuda_runtime.h>
#include <cstdint>

typedef unsigned long long ull;

#define B_   4
#define S_   2048
#define DM_  2048
#define DS_  64
#define REC_ 336   // q[0:64] k[64:128] a[128:192] km[192:256] v[256:320] g,h,c,g2[320:324] pad->336

// ---------------- f32x2 packed helpers ----------------
__device__ __forceinline__ ull fma2(ull a, ull b, ull c) {
    ull d; asm("fma.rn.f32x2 %0,%1,%2,%3;" : "=l"(d) : "l"(a), "l"(b), "l"(c)); return d;
}
__device__ __forceinline__ ull mul2(ull a, ull b) {
    ull d; asm("mul.rn.f32x2 %0,%1,%2;" : "=l"(d) : "l"(a), "l"(b)); return d;
}
__device__ __forceinline__ ull add2(ull a, ull b) {
    ull d; asm("add.rn.f32x2 %0,%1,%2;" : "=l"(d) : "l"(a), "l"(b)); return d;
}
__device__ __forceinline__ ull pack2(float lo, float hi) {
    ull d; asm("mov.b64 %0, {%1,%2};" : "=l"(d) : "f"(lo), "f"(hi)); return d;
}
__device__ __forceinline__ float2 unpack2(ull a) {
    float lo, hi; asm("mov.b64 {%0,%1}, %2;" : "=f"(lo), "=f"(hi) : "l"(a));
    return make_float2(lo, hi);
}

// ---------------- cp.async ----------------
__device__ __forceinline__ void cp_async16(void* smem, const void* gmem) {
    uint32_t s = (uint32_t)__cvta_generic_to_shared(smem);
    asm volatile("cp.async.cg.shared.global [%0], [%1], 16;" :: "r"(s), "l"(gmem) : "memory");
}
#define CP_COMMIT()  asm volatile("cp.async.commit_group;" ::: "memory")
#define CP_WAIT3()   asm volatile("cp.async.wait_group 3;" ::: "memory")
#define BAR0()       asm volatile("bar.sync 0;" ::: "memory")

// ---------------- scratch ----------------
__device__ float g_raw[B_ * S_ * 256];
__device__ float g_inp[B_ * S_ * REC_];
__device__ float g_y  [B_ * S_ * DS_];

// =====================================================================
// Kernel A: projection GEMM (proven)
// =====================================================================
#define BM 64
#define BN 64
#define BK 32

__global__ void __launch_bounds__(256) proj_gemm(
    const float* __restrict__ x,
    const float* __restrict__ Wk, const float* __restrict__ Wv,
    const float* __restrict__ Wq, const float* __restrict__ Wa)
{
    __shared__ __align__(16) float As[BK][BM + 4];
    __shared__ __align__(16) float Bs[BK][BN + 4];

    const int mt = blockIdx.x;
    const int nt = blockIdx.y;
    const float* W = (nt == 0) ? Wk : (nt == 1) ? Wv : (nt == 2) ? Wq : Wa;

    const int tid  = threadIdx.x;
    const int lrow = tid >> 2;
    const int lk   = (tid & 3) * 4;
    const float* xg = x + (size_t)(mt * BM + lrow) * DM_ + lk;
    const float* wg = W + (size_t)lrow * DM_ + lk;

    const int tn4 = (tid & 15) * 4;
    const int tm4 = (tid >> 4) * 4;

    ull acc[4][2];
    #pragma unroll
    for (int i = 0; i < 4; i++) { acc[i][0] = 0ull; acc[i][1] = 0ull; }

    float4 av0 = *(const float4*)xg;
    float4 av1 = *(const float4*)(xg + 16);
    float4 bv0 = *(const float4*)wg;
    float4 bv1 = *(const float4*)(wg + 16);

    for (int k0 = 0; k0 < DM_; k0 += BK) {
        __syncthreads();
        As[lk + 0][lrow] = av0.x; As[lk + 1][lrow] = av0.y;
        As[lk + 2][lrow] = av0.z; As[lk + 3][lrow] = av0.w;
        As[lk + 16][lrow] = av1.x; As[lk + 17][lrow] = av1.y;
        As[lk + 18][lrow] = av1.z; As[lk + 19][lrow] = av1.w;
        Bs[lk + 0][lrow] = bv0.x; Bs[lk + 1][lrow] = bv0.y;
        Bs[lk + 2][lrow] = bv0.z; Bs[lk + 3][lrow] = bv0.w;
        Bs[lk + 16][lrow] = bv1.x; Bs[lk + 17][lrow] = bv1.y;
        Bs[lk + 18][lrow] = bv1.z; Bs[lk + 19][lrow] = bv1.w;
        if (k0 + BK < DM_) {
            av0 = *(const float4*)(xg + k0 + BK);
            av1 = *(const float4*)(xg + k0 + BK + 16);
            bv0 = *(const float4*)(wg + k0 + BK);
            bv1 = *(const float4*)(wg + k0 + BK + 16);
        }
        __syncthreads();
        #pragma unroll
        for (int kk = 0; kk < BK; kk++) {
            ulonglong2 bb = *(const ulonglong2*)&Bs[kk][tn4];
            float4 a4 = *(const float4*)&As[kk][tm4];
            ull p0 = pack2(a4.x, a4.x), p1 = pack2(a4.y, a4.y);
            ull p2 = pack2(a4.z, a4.z), p3 = pack2(a4.w, a4.w);
            acc[0][0] = fma2(p0, bb.x, acc[0][0]); acc[0][1] = fma2(p0, bb.y, acc[0][1]);
            acc[1][0] = fma2(p1, bb.x, acc[1][0]); acc[1][1] = fma2(p1, bb.y, acc[1][1]);
            acc[2][0] = fma2(p2, bb.x, acc[2][0]); acc[2][1] = fma2(p2, bb.y, acc[2][1]);
            acc[3][0] = fma2(p3, bb.x, acc[3][0]); acc[3][1] = fma2(p3, bb.y, acc[3][1]);
        }
    }

    #pragma unroll
    for (int i = 0; i < 4; i++) {
        int m = mt * BM + tm4 + i;
        #pragma unroll
        for (int j = 0; j < 2; j++) {
            float2 f = unpack2(acc[i][j]);
            *(float2*)&g_raw[(size_t)m * 256 + nt * 64 + tn4 + 2 * j] = f;
        }
    }
}

// =====================================================================
// Kernel B: per-token prep (proven)
// =====================================================================
__global__ void __launch_bounds__(256) prep_kernel(
    const float* __restrict__ Wa_b, const float* __restrict__ lam)
{
    const int g    = blockIdx.x * 8 + (threadIdx.x >> 5);
    const int lane = threadIdx.x & 31;
    const float* r_ = g_raw + (size_t)g * 256;

    float k0 = r_[lane],        k1 = r_[lane + 32];
    float v0 = r_[64 + lane],   v1 = r_[96 + lane];
    float q0 = r_[128 + lane],  q1 = r_[160 + lane];
    float z0 = r_[192 + lane] + Wa_b[lane];
    float z1 = r_[224 + lane] + Wa_b[lane + 32];

    float kn = k0 * k0 + k1 * k1;
    #pragma unroll
    for (int m = 1; m < 32; m <<= 1) kn += __shfl_xor_sync(~0u, kn, m);
    float kinv = 1.0f / fmaxf(sqrtf(kn), 1e-12f);
    k0 *= kinv; k1 *= kinv;

    float qn = q0 * q0 + q1 * q1;
    #pragma unroll
    for (int m = 1; m < 32; m <<= 1) qn += __shfl_xor_sync(~0u, qn, m);
    float qinv = 1.0f / fmaxf(sqrtf(qn), 1e-12f);
    q0 *= qinv; q1 *= qinv;

    float la0 = logf(1.0f / (1.0f + expf(-lam[lane])) + 1e-8f);
    float la1 = logf(1.0f / (1.0f + expf(-lam[lane + 32])) + 1e-8f);
    float rr0 = 1.0f / (1.0f + expf(-z0));
    float rr1 = 1.0f / (1.0f + expf(-z1));
    float al0 = expf(8.0f * rr0 * la0);
    float al1 = expf(8.0f * rr1 * la1);
    float km0 = k0 * (1.0f - al0), km1 = k1 * (1.0f - al1);

    float c = q0 * km0 + q1 * km1;
    #pragma unroll
    for (int m = 1; m < 32; m <<= 1) c += __shfl_xor_sync(~0u, c, m);

    float* o = g_inp + (size_t)g * REC_;
    o[lane] = q0;          o[lane + 32] = q1;
    o[64 + lane] = k0;     o[96 + lane] = k1;
    o[128 + lane] = al0;   o[160 + lane] = al1;
    o[192 + lane] = km0;   o[224 + lane] = km1;
    o[256 + lane] = v0;    o[288 + lane] = v1;
    if (lane == 0) o[322] = c;
}

// =====================================================================
// Kernel B2: scalars vs km_{t-1}: g = q.km', h = k.km', g2 = (q.a).km'
// =====================================================================
__global__ void __launch_bounds__(256) ghc_kernel()
{
    const int g    = blockIdx.x * 8 + (threadIdx.x >> 5);
    const int lane = threadIdx.x & 31;
    const int t    = g & (S_ - 1);
    float* cur = g_inp + (size_t)g * REC_;

    float m0 = 0.0f, m1 = 0.0f;
    if (t > 0) {
        const float* prev = cur - REC_;
        m0 = prev[192 + lane]; m1 = prev[224 + lane];
    }
    float q0 = cur[lane],        q1 = cur[lane + 32];
    float k0 = cur[64 + lane],   k1 = cur[96 + lane];
    float a0 = cur[128 + lane],  a1 = cur[160 + lane];

    float gq = q0 * m0 + q1 * m1;
    float gh = k0 * m0 + k1 * m1;
    float g2 = q0 * a0 * m0 + q1 * a1 * m1;
    #pragma unroll
    for (int m = 1; m < 32; m <<= 1) {
        gq += __shfl_xor_sync(~0u, gq, m);
        gh += __shfl_xor_sync(~0u, gh, m);
        g2 += __shfl_xor_sync(~0u, g2, m);
    }
    if (lane == 0) { cur[320] = gq; cur[321] = gh; cur[323] = g2; }
}

// =====================================================================
// Kernel C: warp-specialized scan, R8 structure, unroll x2 + packed STS.
// 4 CTAs x 288 threads. Warps 0-7: vector (2 v x 8 k). Warp 8: sequencer.
// =====================================================================
__device__ __forceinline__ void ld4(ull* d, const float* p) {
    ulonglong2 t0 = *(const ulonglong2*)(p);
    ulonglong2 t1 = *(const ulonglong2*)(p + 4);
    d[0] = t0.x; d[1] = t0.y; d[2] = t1.x; d[3] = t1.y;
}

__global__ void __launch_bounds__(288, 1) scan_kernel()
{
    __shared__ __align__(16) float      stage[8][REC_];
    __shared__ __align__(16) ulonglong2 partAC[2][64 * 9];  // (A2, C2) per (v,kg), stride-9 pad
    __shared__ __align__(16) ull        partY [2][64 * 9];  // Y2 per (v,kg)
    __shared__ __align__(16) float2     swbuf[2][64];       // (sw, sw) per v

    const int b   = blockIdx.x;
    const int tid = threadIdx.x;
    const float* base = g_inp + (size_t)b * S_ * REC_;
    float* yb = g_y + (size_t)b * S_ * DS_;

    if (tid < 64) swbuf[0][tid] = make_float2(0.0f, 0.0f);
    for (int i = tid; i < 64 * 9; i += 288) {
        partAC[0][i] = make_ulonglong2(0ull, 0ull);
        partY [0][i] = 0ull;
    }

    #pragma unroll
    for (int t = 0; t < 6; t++) {
        if (tid < 84) cp_async16(&stage[t][tid * 4], base + (size_t)t * REC_ + tid * 4);
        CP_COMMIT();
    }
    CP_WAIT3();
    __syncthreads();

    if (tid < 256) {
        // ===== vector warps: 2 v x 8 k per thread, ping-pong a/km regs =====
        const int kg = tid & 7;
        const int vp = tid >> 3;
        const int v0 = vp * 2;
        const int ko = kg * 8;
        const int pi0 = v0 * 9 + kg;

        ull Ha0[4], Ha1[4], acE[4], acO[4], kmE[4], kmO[4];
        ld4(acE, stage[0] + 128 + ko);     // a_0
        #pragma unroll
        for (int j = 0; j < 4; j++) { Ha0[j] = 0ull; Ha1[j] = 0ull; kmE[j] = 0ull; }

        for (int i = 0; i < S_; i += 2) {
            // ---------- even step i: uses acE (a_i), kmE (km_{i-1}) ----------
            {
                const float* rc = stage[i & 7];
                const float* rn = stage[(i + 1) & 7];

                if (tid < 84 && i + 6 < S_)
                    cp_async16(&stage[(i + 6) & 7][tid * 4],
                               base + (size_t)(i + 6) * REC_ + tid * 4);
                CP_COMMIT();

                ulonglong2 swp = *(const ulonglong2*)&swbuf[0][v0];
                #pragma unroll
                for (int j = 0; j < 4; j++) {
                    Ha0[j] = mul2(acE[j], fma2(kmE[j], swp.x, Ha0[j]));
                    Ha1[j] = mul2(acE[j], fma2(kmE[j], swp.y, Ha1[j]));
                }

                ld4(kmO, rc + 192 + ko);       // km_i -> used by odd step
                ull qn[4], knn[4];
                ld4(qn,  rn + ko);
                ld4(knn, rn + 64 + ko);
                ld4(acO, rn + 128 + ko);       // a_{i+1} -> used by odd step
                ull qa0 = mul2(qn[0], acO[0]), qa1 = mul2(qn[1], acO[1]);
                ull qa2 = mul2(qn[2], acO[2]), qa3 = mul2(qn[3], acO[3]);

                ull A0 = mul2(qn[0], Ha0[0]), A1 = mul2(qn[0], Ha1[0]);
                ull C0 = mul2(knn[0], Ha0[0]), C1 = mul2(knn[0], Ha1[0]);
                ull Y0 = mul2(qa0, Ha0[0]),   Y1 = mul2(qa0, Ha1[0]);
                A0 = fma2(qn[1], Ha0[1], A0);  A1 = fma2(qn[1], Ha1[1], A1);
                C0 = fma2(knn[1], Ha0[1], C0); C1 = fma2(knn[1], Ha1[1], C1);
                Y0 = fma2(qa1, Ha0[1], Y0);    Y1 = fma2(qa1, Ha1[1], Y1);
                A0 = fma2(qn[2], Ha0[2], A0);  A1 = fma2(qn[2], Ha1[2], A1);
                C0 = fma2(knn[2], Ha0[2], C0); C1 = fma2(knn[2], Ha1[2], C1);
                Y0 = fma2(qa2, Ha0[2], Y0);    Y1 = fma2(qa2, Ha1[2], Y1);
                A0 = fma2(qn[3], Ha0[3], A0);  A1 = fma2(qn[3], Ha1[3], A1);
                C0 = fma2(knn[3], Ha0[3], C0); C1 = fma2(knn[3], Ha1[3], C1);
                Y0 = fma2(qa3, Ha0[3], Y0);    Y1 = fma2(qa3, Ha1[3], Y1);

                partAC[1][pi0]     = make_ulonglong2(A0, C0);
                partAC[1][pi0 + 9] = make_ulonglong2(A1, C1);
                partY [1][pi0]     = Y0;
                partY [1][pi0 + 9] = Y1;

                CP_WAIT3();
                BAR0();
            }
            // ---------- odd step i+1: uses acO (a_{i+1}), kmO (km_i) ----------
            {
                const float* rc = stage[(i + 1) & 7];
                const float* rn = stage[(i + 2) & 7];

                if (tid < 84 && i + 7 < S_)
                    cp_async16(&stage[(i + 7) & 7][tid * 4],
                               base + (size_t)(i + 7) * REC_ + tid * 4);
                CP_COMMIT();

                ulonglong2 swp = *(const ulonglong2*)&swbuf[1][v0];
                #pragma unroll
                for (int j = 0; j < 4; j++) {
                    Ha0[j] = mul2(acO[j], fma2(kmO[j], swp.x, Ha0[j]));
                    Ha1[j] = mul2(acO[j], fma2(kmO[j], swp.y, Ha1[j]));
                }

                ld4(kmE, rc + 192 + ko);       // km_{i+1} -> next even step
                ull qn[4], knn[4];
                ld4(qn,  rn + ko);
                ld4(knn, rn + 64 + ko);
                ld4(acE, rn + 128 + ko);       // a_{i+2} -> next even step
                ull qa0 = mul2(qn[0], acE[0]), qa1 = mul2(qn[1], acE[1]);
                ull qa2 = mul2(qn[2], acE[2]), qa3 = mul2(qn[3], acE[3]);

                ull A0 = mul2(qn[0], Ha0[0]), A1 = mul2(qn[0], Ha1[0]);
                ull C0 = mul2(knn[0], Ha0[0]), C1 = mul2(knn[0], Ha1[0]);
                ull Y0 = mul2(qa0, Ha0[0]),   Y1 = mul2(qa0, Ha1[0]);
                A0 = fma2(qn[1], Ha0[1], A0);  A1 = fma2(qn[1], Ha1[1], A1);
                C0 = fma2(knn[1], Ha0[1], C0); C1 = fma2(knn[1], Ha1[1], C1);
                Y0 = fma2(qa1, Ha0[1], Y0);    Y1 = fma2(qa1, Ha1[1], Y1);
                A0 = fma2(qn[2], Ha0[2], A0);  A1 = fma2(qn[2], Ha1[2], A1);
                C0 = fma2(knn[2], Ha0[2], C0); C1 = fma2(knn[2], Ha1[2], C1);
                Y0 = fma2(qa2, Ha0[2], Y0);    Y1 = fma2(qa2, Ha1[2], Y1);
                A0 = fma2(qn[3], Ha0[3], A0);  A1 = fma2(qn[3], Ha1[3], A1);
                C0 = fma2(knn[3], Ha0[3], C0); C1 = fma2(knn[3], Ha1[3], C1);
                Y0 = fma2(qa3, Ha0[3], Y0);    Y1 = fma2(qa3, Ha1[3], Y1);

                partAC[0][pi0]     = make_ulonglong2(A0, C0);
                partAC[0][pi0 + 9] = make_ulonglong2(A1, C1);
                partY [0][pi0]     = Y0;
                partY [0][pi0 + 9] = Y1;

                CP_WAIT3();
                BAR0();
            }
        }
    } else {
        // ===== sequencer warp =====
        const int lane = tid - 256;
        float w0 = 0.0f, w1 = 0.0f, sprev = 0.0f;

        for (int i = 0; i < S_; i++) {
            const float* rc = stage[i & 7];
            const ulonglong2* pac = partAC[i & 1];
            const ull* py = partY[i & 1];

            ulonglong2 a0 = pac[lane * 9 + 0], a1 = pac[lane * 9 + 1];
            ulonglong2 a2 = pac[lane * 9 + 2], a3 = pac[lane * 9 + 3];
            ulonglong2 a4 = pac[lane * 9 + 4], a5 = pac[lane * 9 + 5];
            ulonglong2 a6 = pac[lane * 9 + 6], a7 = pac[lane * 9 + 7];
            ulonglong2 b0 = pac[(lane + 32) * 9 + 0], b1 = pac[(lane + 32) * 9 + 1];
            ulonglong2 b2 = pac[(lane + 32) * 9 + 2], b3 = pac[(lane + 32) * 9 + 3];
            ulonglong2 b4 = pac[(lane + 32) * 9 + 4], b5 = pac[(lane + 32) * 9 + 5];
            ulonglong2 b6 = pac[(lane + 32) * 9 + 6], b7 = pac[(lane + 32) * 9 + 7];

            ull A2a = add2(add2(add2(a0.x, a1.x), add2(a2.x, a3.x)),
                           add2(add2(a4.x, a5.x), add2(a6.x, a7.x)));
            ull C2a = add2(add2(add2(a0.y, a1.y), add2(a2.y, a3.y)),
                           add2(add2(a4.y, a5.y), add2(a6.y, a7.y)));
            ull A2b = add2(add2(add2(b0.x, b1.x), add2(b2.x, b3.x)),
                           add2(add2(b4.x, b5.x), add2(b6.x, b7.x)));
            ull C2b = add2(add2(add2(b0.y, b1.y), add2(b2.y, b3.y)),
                           add2(add2(b4.y, b5.y), add2(b6.y, b7.y)));
            ull Y2a = add2(add2(add2(py[lane * 9 + 0], py[lane * 9 + 1]),
                                add2(py[lane * 9 + 2], py[lane * 9 + 3])),
                           add2(add2(py[lane * 9 + 4], py[lane * 9 + 5]),
                                add2(py[lane * 9 + 6], py[lane * 9 + 7])));
            ull Y2b = add2(add2(add2(py[(lane + 32) * 9 + 0], py[(lane + 32) * 9 + 1]),
                                add2(py[(lane + 32) * 9 + 2], py[(lane + 32) * 9 + 3])),
                           add2(add2(py[(lane + 32) * 9 + 4], py[(lane + 32) * 9 + 5]),
                                add2(py[(lane + 32) * 9 + 6], py[(lane + 32) * 9 + 7])));

            float2 fA0 = unpack2(A2a), fC0 = unpack2(C2a), fY0 = unpack2(Y2a);
            float2 fA1 = unpack2(A2b), fC1 = unpack2(C2b), fY1 = unpack2(Y2b);
            float A0 = fA0.x + fA0.y, C0 = fC0.x + fC0.y, Y0 = fY0.x + fY0.y;
            float A1 = fA1.x + fA1.y, C1 = fC1.x + fC1.y, Y1 = fY1.x + fY1.y;

            float v0 = rc[256 + lane], v1 = rc[288 + lane];
            float4 sc = *(const float4*)&rc[320];   // g, h, c, g2

            float sg = sprev * sc.x;
            float sh = sprev * sc.y;
            float u0 = v0 - A0 - sg * w0;
            float u1 = v1 - A1 - sg * w1;
            float e = u0 * u0 + u1 * u1;
            e += __shfl_xor_sync(~0u, e, 1);
            e += __shfl_xor_sync(~0u, e, 2);
            e += __shfl_xor_sync(~0u, e, 4);
            e += __shfl_xor_sync(~0u, e, 8);
            e += __shfl_xor_sync(~0u, e, 16);
            float s;
            asm("tanh.approx.f32 %0, %1;" : "=f"(s) : "f"(e * 0.499999495f));
            s = fmaf(0.5f, s, 0.5f);

            float t20 = sprev * sc.w * w0;
            float t21 = sprev * sc.w * w1;
            w0 = (v0 - C0) - sh * w0;
            w1 = (v1 - C1) - sh * w1;
            float sw0 = s * w0, sw1 = s * w1;
            swbuf[(i + 1) & 1][lane]      = make_float2(sw0, sw0);
            swbuf[(i + 1) & 1][lane + 32] = make_float2(sw1, sw1);

            yb[(size_t)i * DS_ + lane]      = Y0 + t20 + s * sc.z * w0;
            yb[(size_t)i * DS_ + lane + 32] = Y1 + t21 + s * sc.z * w1;

            sprev = s;
            BAR0();
        }
    }
}

// =====================================================================
// Kernel D: RMS-norm(y)*norm_w @ Wo^T -> out (proven)
// =====================================================================
__global__ void __launch_bounds__(256) out_gemm(
    const float* __restrict__ norm_w, const float* __restrict__ Wo,
    float* __restrict__ out)
{
    __shared__ __align__(16) float ys[32 * 64];
    __shared__ __align__(16) float wos[64 * 128];
    __shared__ float rs[32];
    __shared__ float nws[64];

    const int tid = threadIdx.x;
    const int m0 = blockIdx.y * 32;
    const int n0 = blockIdx.x * 128;

    for (int i = tid * 4; i < 2048; i += 1024)
        *(float4*)&ys[i] = *(const float4*)&g_y[(size_t)m0 * 64 + i];
    if (tid < 64) nws[tid] = norm_w[tid];
    {
        int n  = tid & 127;
        int vb = tid >> 7;
        #pragma unroll
        for (int q = 0; q < 8; q++) {
            int v4 = vb * 8 + q;
            float4 w = *(const float4*)&Wo[(size_t)(n0 + n) * 64 + v4 * 4];
            wos[(v4 * 4 + 0) * 128 + n] = w.x;
            wos[(v4 * 4 + 1) * 128 + n] = w.y;
            wos[(v4 * 4 + 2) * 128 + n] = w.z;
            wos[(v4 * 4 + 3) * 128 + n] = w.w;
        }
    }
    __syncthreads();

    {
        int r = tid >> 3, p = tid & 7;
        float sum = 0.0f;
        #pragma unroll
        for (int j = 0; j < 8; j++) { float x = ys[r * 64 + p * 8 + j]; sum += x * x; }
        sum += __shfl_xor_sync(~0u, sum, 1);
        sum += __shfl_xor_sync(~0u, sum, 2);
        sum += __shfl_xor_sync(~0u, sum, 4);
        if (p == 0) rs[r] = rsqrtf(sum * (1.0f / 64.0f) + 1e-6f);
    }
    __syncthreads();
    for (int i = tid; i < 2048; i += 256)
        ys[i] = ys[i] * rs[i >> 6] * nws[i & 63];
    __syncthreads();

    const int tn = tid & 31;
    const int tm = tid >> 5;
    float acc[4][4];
    #pragma unroll
    for (int i = 0; i < 4; i++)
        #pragma unroll
        for (int j = 0; j < 4; j++) acc[i][j] = 0.0f;

    #pragma unroll 8
    for (int vv = 0; vv < 64; vv++) {
        float b0 = wos[vv * 128 + tn];
        float b1 = wos[vv * 128 + tn + 32];
        float b2 = wos[vv * 128 + tn + 64];
        float b3 = wos[vv * 128 + tn + 96];
        #pragma unroll
        for (int i = 0; i < 4; i++) {
            float a = ys[(tm * 4 + i) * 64 + vv];
            acc[i][0] += a * b0; acc[i][1] += a * b1;
            acc[i][2] += a * b2; acc[i][3] += a * b3;
        }
    }
    #pragma unroll
    for (int i = 0; i < 4; i++) {
        size_t row = (size_t)(m0 + tm * 4 + i) * 2048 + n0 + tn;
        #pragma unroll
        for (int j = 0; j < 4; j++) out[row + 32 * j] = acc[i][j];
    }
}

// =====================================================================
extern "C" void kernel_launch(void* const* d_in, const int* in_sizes, int n_in,
                              void* d_out, int out_size)
{
    const float* x      = (const float*)d_in[0];
    const float* Wk     = (const float*)d_in[1];
    const float* Wv     = (const float*)d_in[2];
    const float* Wq     = (const float*)d_in[3];
    const float* Wa_w   = (const float*)d_in[4];
    const float* Wa_b   = (const float*)d_in[5];
    const float* lam    = (const float*)d_in[6];
    const float* norm_w = (const float*)d_in[7];
    const float* Wo     = (const float*)d_in[8];
    float* out = (float*)d_out;

    proj_gemm<<<dim3(128, 4), 256>>>(x, Wk, Wv, Wq, Wa_w);
    prep_kernel<<<1024, 256>>>(Wa_b, lam);
    ghc_kernel<<<1024, 256>>>();
    scan_kernel<<<4, 288>>>();
    out_gemm<<<dim3(16, 256), 256>>>(norm_w, Wo, out);
}

// round 12
// speedup vs baseline: 1.4035x; 1.1160x over previous
#include <cuda_runtime.h>
#include <cstdint>

typedef unsigned long long ull;

#define B_   4
#define S_   2048
#define DM_  2048
#define DS_  64
#define REC_ 336   // q[0:64] k[64:128] a[128:192] km[192:256] v[256:320] g,h,c,g2[320:324] pad->336

// ---------------- f32x2 packed helpers ----------------
__device__ __forceinline__ ull fma2(ull a, ull b, ull c) {
    ull d; asm("fma.rn.f32x2 %0,%1,%2,%3;" : "=l"(d) : "l"(a), "l"(b), "l"(c)); return d;
}
__device__ __forceinline__ ull mul2(ull a, ull b) {
    ull d; asm("mul.rn.f32x2 %0,%1,%2;" : "=l"(d) : "l"(a), "l"(b)); return d;
}
__device__ __forceinline__ ull pack2(float lo, float hi) {
    ull d; asm("mov.b64 %0, {%1,%2};" : "=l"(d) : "f"(lo), "f"(hi)); return d;
}
__device__ __forceinline__ float2 unpack2(ull a) {
    float lo, hi; asm("mov.b64 {%0,%1}, %2;" : "=f"(lo), "=f"(hi) : "l"(a));
    return make_float2(lo, hi);
}

// ---------------- cp.async ----------------
__device__ __forceinline__ void cp_async16(void* smem, const void* gmem) {
    uint32_t s = (uint32_t)__cvta_generic_to_shared(smem);
    asm volatile("cp.async.cg.shared.global [%0], [%1], 16;" :: "r"(s), "l"(gmem) : "memory");
}
#define CP_COMMIT()  asm volatile("cp.async.commit_group;" ::: "memory")
#define CP_WAIT3()   asm volatile("cp.async.wait_group 3;" ::: "memory")
#define BAR0()       asm volatile("bar.sync 0;" ::: "memory")

// ---------------- scratch ----------------
__device__ float g_raw[B_ * S_ * 256];
__device__ float g_inp[B_ * S_ * REC_];
__device__ float g_y  [B_ * S_ * DS_];

// =====================================================================
// Kernel A: projection GEMM (proven)
// =====================================================================
#define BM 64
#define BN 64
#define BK 32

__global__ void __launch_bounds__(256) proj_gemm(
    const float* __restrict__ x,
    const float* __restrict__ Wk, const float* __restrict__ Wv,
    const float* __restrict__ Wq, const float* __restrict__ Wa)
{
    __shared__ __align__(16) float As[BK][BM + 4];
    __shared__ __align__(16) float Bs[BK][BN + 4];

    const int mt = blockIdx.x;
    const int nt = blockIdx.y;
    const float* W = (nt == 0) ? Wk : (nt == 1) ? Wv : (nt == 2) ? Wq : Wa;

    const int tid  = threadIdx.x;
    const int lrow = tid >> 2;
    const int lk   = (tid & 3) * 4;
    const float* xg = x + (size_t)(mt * BM + lrow) * DM_ + lk;
    const float* wg = W + (size_t)lrow * DM_ + lk;

    const int tn4 = (tid & 15) * 4;
    const int tm4 = (tid >> 4) * 4;

    ull acc[4][2];
    #pragma unroll
    for (int i = 0; i < 4; i++) { acc[i][0] = 0ull; acc[i][1] = 0ull; }

    float4 av0 = *(const float4*)xg;
    float4 av1 = *(const float4*)(xg + 16);
    float4 bv0 = *(const float4*)wg;
    float4 bv1 = *(const float4*)(wg + 16);

    for (int k0 = 0; k0 < DM_; k0 += BK) {
        __syncthreads();
        As[lk + 0][lrow] = av0.x; As[lk + 1][lrow] = av0.y;
        As[lk + 2][lrow] = av0.z; As[lk + 3][lrow] = av0.w;
        As[lk + 16][lrow] = av1.x; As[lk + 17][lrow] = av1.y;
        As[lk + 18][lrow] = av1.z; As[lk + 19][lrow] = av1.w;
        Bs[lk + 0][lrow] = bv0.x; Bs[lk + 1][lrow] = bv0.y;
        Bs[lk + 2][lrow] = bv0.z; Bs[lk + 3][lrow] = bv0.w;
        Bs[lk + 16][lrow] = bv1.x; Bs[lk + 17][lrow] = bv1.y;
        Bs[lk + 18][lrow] = bv1.z; Bs[lk + 19][lrow] = bv1.w;
        if (k0 + BK < DM_) {
            av0 = *(const float4*)(xg + k0 + BK);
            av1 = *(const float4*)(xg + k0 + BK + 16);
            bv0 = *(const float4*)(wg + k0 + BK);
            bv1 = *(const float4*)(wg + k0 + BK + 16);
        }
        __syncthreads();
        #pragma unroll
        for (int kk = 0; kk < BK; kk++) {
            ulonglong2 bb = *(const ulonglong2*)&Bs[kk][tn4];
            float4 a4 = *(const float4*)&As[kk][tm4];
            ull p0 = pack2(a4.x, a4.x), p1 = pack2(a4.y, a4.y);
            ull p2 = pack2(a4.z, a4.z), p3 = pack2(a4.w, a4.w);
            acc[0][0] = fma2(p0, bb.x, acc[0][0]); acc[0][1] = fma2(p0, bb.y, acc[0][1]);
            acc[1][0] = fma2(p1, bb.x, acc[1][0]); acc[1][1] = fma2(p1, bb.y, acc[1][1]);
            acc[2][0] = fma2(p2, bb.x, acc[2][0]); acc[2][1] = fma2(p2, bb.y, acc[2][1]);
            acc[3][0] = fma2(p3, bb.x, acc[3][0]); acc[3][1] = fma2(p3, bb.y, acc[3][1]);
        }
    }

    #pragma unroll
    for (int i = 0; i < 4; i++) {
        int m = mt * BM + tm4 + i;
        #pragma unroll
        for (int j = 0; j < 2; j++) {
            float2 f = unpack2(acc[i][j]);
            *(float2*)&g_raw[(size_t)m * 256 + nt * 64 + tn4 + 2 * j] = f;
        }
    }
}

// =====================================================================
// Kernel B: per-token prep (proven)
// =====================================================================
__global__ void __launch_bounds__(256) prep_kernel(
    const float* __restrict__ Wa_b, const float* __restrict__ lam)
{
    const int g    = blockIdx.x * 8 + (threadIdx.x >> 5);
    const int lane = threadIdx.x & 31;
    const float* r_ = g_raw + (size_t)g * 256;

    float k0 = r_[lane],        k1 = r_[lane + 32];
    float v0 = r_[64 + lane],   v1 = r_[96 + lane];
    float q0 = r_[128 + lane],  q1 = r_[160 + lane];
    float z0 = r_[192 + lane] + Wa_b[lane];
    float z1 = r_[224 + lane] + Wa_b[lane + 32];

    float kn = k0 * k0 + k1 * k1;
    #pragma unroll
    for (int m = 1; m < 32; m <<= 1) kn += __shfl_xor_sync(~0u, kn, m);
    float kinv = 1.0f / fmaxf(sqrtf(kn), 1e-12f);
    k0 *= kinv; k1 *= kinv;

    float qn = q0 * q0 + q1 * q1;
    #pragma unroll
    for (int m = 1; m < 32; m <<= 1) qn += __shfl_xor_sync(~0u, qn, m);
    float qinv = 1.0f / fmaxf(sqrtf(qn), 1e-12f);
    q0 *= qinv; q1 *= qinv;

    float la0 = logf(1.0f / (1.0f + expf(-lam[lane])) + 1e-8f);
    float la1 = logf(1.0f / (1.0f + expf(-lam[lane + 32])) + 1e-8f);
    float rr0 = 1.0f / (1.0f + expf(-z0));
    float rr1 = 1.0f / (1.0f + expf(-z1));
    float al0 = expf(8.0f * rr0 * la0);
    float al1 = expf(8.0f * rr1 * la1);
    float km0 = k0 * (1.0f - al0), km1 = k1 * (1.0f - al1);

    float c = q0 * km0 + q1 * km1;
    #pragma unroll
    for (int m = 1; m < 32; m <<= 1) c += __shfl_xor_sync(~0u, c, m);

    float* o = g_inp + (size_t)g * REC_;
    o[lane] = q0;          o[lane + 32] = q1;
    o[64 + lane] = k0;     o[96 + lane] = k1;
    o[128 + lane] = al0;   o[160 + lane] = al1;
    o[192 + lane] = km0;   o[224 + lane] = km1;
    o[256 + lane] = v0;    o[288 + lane] = v1;
    if (lane == 0) o[322] = c;
}

// =====================================================================
// Kernel B2: scalars vs km_{t-1}: g = q.km', h = k.km', g2 = (q.a).km'
// =====================================================================
__global__ void __launch_bounds__(256) ghc_kernel()
{
    const int g    = blockIdx.x * 8 + (threadIdx.x >> 5);
    const int lane = threadIdx.x & 31;
    const int t    = g & (S_ - 1);
    float* cur = g_inp + (size_t)g * REC_;

    float m0 = 0.0f, m1 = 0.0f;
    if (t > 0) {
        const float* prev = cur - REC_;
        m0 = prev[192 + lane]; m1 = prev[224 + lane];
    }
    float q0 = cur[lane],        q1 = cur[lane + 32];
    float k0 = cur[64 + lane],   k1 = cur[96 + lane];
    float a0 = cur[128 + lane],  a1 = cur[160 + lane];

    float gq = q0 * m0 + q1 * m1;
    float gh = k0 * m0 + k1 * m1;
    float g2 = q0 * a0 * m0 + q1 * a1 * m1;
    #pragma unroll
    for (int m = 1; m < 32; m <<= 1) {
        gq += __shfl_xor_sync(~0u, gq, m);
        gh += __shfl_xor_sync(~0u, gh, m);
        g2 += __shfl_xor_sync(~0u, g2, m);
    }
    if (lane == 0) { cur[320] = gq; cur[321] = gh; cur[323] = g2; }
}

// =====================================================================
// Kernel C: warp-specialized scan. R8 structure + ping-pong unroll x2.
// 4 CTAs x 288 threads. Warps 0-7: vector (2 v x 8 k). Warp 8: sequencer.
// Partial format and ALL MIO identical to the 938us R8 kernel.
// =====================================================================
__device__ __forceinline__ void ld4(ull* d, const float* p) {
    ulonglong2 t0 = *(const ulonglong2*)(p);
    ulonglong2 t1 = *(const ulonglong2*)(p + 4);
    d[0] = t0.x; d[1] = t0.y; d[2] = t1.x; d[3] = t1.y;
}

__global__ void __launch_bounds__(288, 1) scan_kernel()
{
    __shared__ __align__(16) float  stage[8][REC_];
    __shared__ __align__(16) float4 part[2][64 * 9];   // [buf][v*9 + kg], stride-9 pad
    __shared__ __align__(16) float2 swbuf[2][64];      // (sw, sw) per v

    const int b   = blockIdx.x;
    const int tid = threadIdx.x;
    const float* base = g_inp + (size_t)b * S_ * REC_;
    float* yb = g_y + (size_t)b * S_ * DS_;

    if (tid < 64) swbuf[0][tid] = make_float2(0.0f, 0.0f);
    for (int i = tid; i < 64 * 9; i += 288)
        part[0][i] = make_float4(0.f, 0.f, 0.f, 0.f);

    #pragma unroll
    for (int t = 0; t < 6; t++) {
        if (tid < 84) cp_async16(&stage[t][tid * 4], base + (size_t)t * REC_ + tid * 4);
        CP_COMMIT();
    }
    CP_WAIT3();
    __syncthreads();

    if (tid < 256) {
        // ===== vector warps: 2 v x 8 k per thread, ping-pong a/km regs =====
        const int kg = tid & 7;
        const int vp = tid >> 3;
        const int v0 = vp * 2;
        const int ko = kg * 8;
        const int pi0 = v0 * 9 + kg;

        ull Ha0[4], Ha1[4], acE[4], acO[4], kmE[4], kmO[4];
        ld4(acE, stage[0] + 128 + ko);     // a_0
        #pragma unroll
        for (int j = 0; j < 4; j++) { Ha0[j] = 0ull; Ha1[j] = 0ull; kmE[j] = 0ull; }

        for (int i = 0; i < S_; i += 2) {
            // ---------- even step i: uses acE (a_i), kmE (km_{i-1}) ----------
            {
                const float* rc = stage[i & 7];
                const float* rn = stage[(i + 1) & 7];

                if (tid < 84 && i + 6 < S_)
                    cp_async16(&stage[(i + 6) & 7][tid * 4],
                               base + (size_t)(i + 6) * REC_ + tid * 4);
                CP_COMMIT();

                ulonglong2 swp = *(const ulonglong2*)&swbuf[0][v0];
                #pragma unroll
                for (int j = 0; j < 4; j++) {
                    Ha0[j] = mul2(acE[j], fma2(kmE[j], swp.x, Ha0[j]));
                    Ha1[j] = mul2(acE[j], fma2(kmE[j], swp.y, Ha1[j]));
                }

                ld4(kmO, rc + 192 + ko);       // km_i -> used by odd step
                ull qn[4], knn[4];
                ld4(qn,  rn + ko);
                ld4(knn, rn + 64 + ko);
                ld4(acO, rn + 128 + ko);       // a_{i+1} -> used by odd step
                ull qa0 = mul2(qn[0], acO[0]), qa1 = mul2(qn[1], acO[1]);
                ull qa2 = mul2(qn[2], acO[2]), qa3 = mul2(qn[3], acO[3]);

                ull A0 = mul2(qn[0], Ha0[0]), A1 = mul2(qn[0], Ha1[0]);
                ull C0 = mul2(knn[0], Ha0[0]), C1 = mul2(knn[0], Ha1[0]);
                ull Y0 = mul2(qa0, Ha0[0]),   Y1 = mul2(qa0, Ha1[0]);
                A0 = fma2(qn[1], Ha0[1], A0);  A1 = fma2(qn[1], Ha1[1], A1);
                C0 = fma2(knn[1], Ha0[1], C0); C1 = fma2(knn[1], Ha1[1], C1);
                Y0 = fma2(qa1, Ha0[1], Y0);    Y1 = fma2(qa1, Ha1[1], Y1);
                A0 = fma2(qn[2], Ha0[2], A0);  A1 = fma2(qn[2], Ha1[2], A1);
                C0 = fma2(knn[2], Ha0[2], C0); C1 = fma2(knn[2], Ha1[2], C1);
                Y0 = fma2(qa2, Ha0[2], Y0);    Y1 = fma2(qa2, Ha1[2], Y1);
                A0 = fma2(qn[3], Ha0[3], A0);  A1 = fma2(qn[3], Ha1[3], A1);
                C0 = fma2(knn[3], Ha0[3], C0); C1 = fma2(knn[3], Ha1[3], C1);
                Y0 = fma2(qa3, Ha0[3], Y0);    Y1 = fma2(qa3, Ha1[3], Y1);

                float2 fa0 = unpack2(A0), fc0 = unpack2(C0), fy0 = unpack2(Y0);
                float2 fa1 = unpack2(A1), fc1 = unpack2(C1), fy1 = unpack2(Y1);
                part[1][pi0] =
                    make_float4(fa0.x + fa0.y, fc0.x + fc0.y, fy0.x + fy0.y, 0.0f);
                part[1][pi0 + 9] =
                    make_float4(fa1.x + fa1.y, fc1.x + fc1.y, fy1.x + fy1.y, 0.0f);

                CP_WAIT3();
                BAR0();
            }
            // ---------- odd step i+1: uses acO (a_{i+1}), kmO (km_i) ----------
            {
                const float* rc = stage[(i + 1) & 7];
                const float* rn = stage[(i + 2) & 7];

                if (tid < 84 && i + 7 < S_)
                    cp_async16(&stage[(i + 7) & 7][tid * 4],
                               base + (size_t)(i + 7) * REC_ + tid * 4);
                CP_COMMIT();

                ulonglong2 swp = *(const ulonglong2*)&swbuf[1][v0];
                #pragma unroll
                for (int j = 0; j < 4; j++) {
                    Ha0[j] = mul2(acO[j], fma2(kmO[j], swp.x, Ha0[j]));
                    Ha1[j] = mul2(acO[j], fma2(kmO[j], swp.y, Ha1[j]));
                }

                ld4(kmE, rc + 192 + ko);       // km_{i+1} -> next even step
                ull qn[4], knn[4];
                ld4(qn,  rn + ko);
                ld4(knn, rn + 64 + ko);
                ld4(acE, rn + 128 + ko);       // a_{i+2} -> next even step
                ull qa0 = mul2(qn[0], acE[0]), qa1 = mul2(qn[1], acE[1]);
                ull qa2 = mul2(qn[2], acE[2]), qa3 = mul2(qn[3], acE[3]);

                ull A0 = mul2(qn[0], Ha0[0]), A1 = mul2(qn[0], Ha1[0]);
                ull C0 = mul2(knn[0], Ha0[0]), C1 = mul2(knn[0], Ha1[0]);
                ull Y0 = mul2(qa0, Ha0[0]),   Y1 = mul2(qa0, Ha1[0]);
                A0 = fma2(qn[1], Ha0[1], A0);  A1 = fma2(qn[1], Ha1[1], A1);
                C0 = fma2(knn[1], Ha0[1], C0); C1 = fma2(knn[1], Ha1[1], C1);
                Y0 = fma2(qa1, Ha0[1], Y0);    Y1 = fma2(qa1, Ha1[1], Y1);
                A0 = fma2(qn[2], Ha0[2], A0);  A1 = fma2(qn[2], Ha1[2], A1);
                C0 = fma2(knn[2], Ha0[2], C0); C1 = fma2(knn[2], Ha1[2], C1);
                Y0 = fma2(qa2, Ha0[2], Y0);    Y1 = fma2(qa2, Ha1[2], Y1);
                A0 = fma2(qn[3], Ha0[3], A0);  A1 = fma2(qn[3], Ha1[3], A1);
                C0 = fma2(knn[3], Ha0[3], C0); C1 = fma2(knn[3], Ha1[3], C1);
                Y0 = fma2(qa3, Ha0[3], Y0);    Y1 = fma2(qa3, Ha1[3], Y1);

                float2 fa0 = unpack2(A0), fc0 = unpack2(C0), fy0 = unpack2(Y0);
                float2 fa1 = unpack2(A1), fc1 = unpack2(C1), fy1 = unpack2(Y1);
                part[0][pi0] =
                    make_float4(fa0.x + fa0.y, fc0.x + fc0.y, fy0.x + fy0.y, 0.0f);
                part[0][pi0 + 9] =
                    make_float4(fa1.x + fa1.y, fc1.x + fc1.y, fy1.x + fy1.y, 0.0f);

                CP_WAIT3();
                BAR0();
            }
        }
    } else {
        // ===== sequencer warp (identical to R8) =====
        const int lane = tid - 256;
        float w0 = 0.0f, w1 = 0.0f, sprev = 0.0f;

        for (int i = 0; i < S_; i++) {
            const float* rc = stage[i & 7];
            const float4* pp = part[i & 1];

            float4 x0 = pp[lane * 9 + 0], x1 = pp[lane * 9 + 1];
            float4 x2 = pp[lane * 9 + 2], x3 = pp[lane * 9 + 3];
            float4 x4 = pp[lane * 9 + 4], x5 = pp[lane * 9 + 5];
            float4 x6 = pp[lane * 9 + 6], x7 = pp[lane * 9 + 7];
            float4 z0 = pp[(lane + 32) * 9 + 0], z1 = pp[(lane + 32) * 9 + 1];
            float4 z2 = pp[(lane + 32) * 9 + 2], z3 = pp[(lane + 32) * 9 + 3];
            float4 z4 = pp[(lane + 32) * 9 + 4], z5 = pp[(lane + 32) * 9 + 5];
            float4 z6 = pp[(lane + 32) * 9 + 6], z7 = pp[(lane + 32) * 9 + 7];

            float A0 = ((x0.x + x1.x) + (x2.x + x3.x)) + ((x4.x + x5.x) + (x6.x + x7.x));
            float C0 = ((x0.y + x1.y) + (x2.y + x3.y)) + ((x4.y + x5.y) + (x6.y + x7.y));
            float Y0 = ((x0.z + x1.z) + (x2.z + x3.z)) + ((x4.z + x5.z) + (x6.z + x7.z));
            float A1 = ((z0.x + z1.x) + (z2.x + z3.x)) + ((z4.x + z5.x) + (z6.x + z7.x));
            float C1 = ((z0.y + z1.y) + (z2.y + z3.y)) + ((z4.y + z5.y) + (z6.y + z7.y));
            float Y1 = ((z0.z + z1.z) + (z2.z + z3.z)) + ((z4.z + z5.z) + (z6.z + z7.z));

            float v0 = rc[256 + lane], v1 = rc[288 + lane];
            float4 sc = *(const float4*)&rc[320];   // g, h, c, g2

            float sg = sprev * sc.x;
            float sh = sprev * sc.y;
            float u0 = v0 - A0 - sg * w0;
            float u1 = v1 - A1 - sg * w1;
            float e = u0 * u0 + u1 * u1;
            e += __shfl_xor_sync(~0u, e, 1);
            e += __shfl_xor_sync(~0u, e, 2);
            e += __shfl_xor_sync(~0u, e, 4);
            e += __shfl_xor_sync(~0u, e, 8);
            e += __shfl_xor_sync(~0u, e, 16);
            float s;
            asm("tanh.approx.f32 %0, %1;" : "=f"(s) : "f"(e * 0.499999495f));
            s = fmaf(0.5f, s, 0.5f);

            float t20 = sprev * sc.w * w0;
            float t21 = sprev * sc.w * w1;
            w0 = (v0 - C0) - sh * w0;
            w1 = (v1 - C1) - sh * w1;
            float sw0 = s * w0, sw1 = s * w1;
            swbuf[(i + 1) & 1][lane]      = make_float2(sw0, sw0);
            swbuf[(i + 1) & 1][lane + 32] = make_float2(sw1, sw1);

            yb[(size_t)i * DS_ + lane]      = Y0 + t20 + s * sc.z * w0;
            yb[(size_t)i * DS_ + lane + 32] = Y1 + t21 + s * sc.z * w1;

            sprev = s;
            BAR0();
        }
    }
}

// =====================================================================
// Kernel D: RMS-norm(y)*norm_w @ Wo^T -> out (proven)
// =====================================================================
__global__ void __launch_bounds__(256) out_gemm(
    const float* __restrict__ norm_w, const float* __restrict__ Wo,
    float* __restrict__ out)
{
    __shared__ __align__(16) float ys[32 * 64];
    __shared__ __align__(16) float wos[64 * 128];
    __shared__ float rs[32];
    __shared__ float nws[64];

    const int tid = threadIdx.x;
    const int m0 = blockIdx.y * 32;
    const int n0 = blockIdx.x * 128;

    for (int i = tid * 4; i < 2048; i += 1024)
        *(float4*)&ys[i] = *(const float4*)&g_y[(size_t)m0 * 64 + i];
    if (tid < 64) nws[tid] = norm_w[tid];
    {
        int n  = tid & 127;
        int vb = tid >> 7;
        #pragma unroll
        for (int q = 0; q < 8; q++) {
            int v4 = vb * 8 + q;
            float4 w = *(const float4*)&Wo[(size_t)(n0 + n) * 64 + v4 * 4];
            wos[(v4 * 4 + 0) * 128 + n] = w.x;
            wos[(v4 * 4 + 1) * 128 + n] = w.y;
            wos[(v4 * 4 + 2) * 128 + n] = w.z;
            wos[(v4 * 4 + 3) * 128 + n] = w.w;
        }
    }
    __syncthreads();

    {
        int r = tid >> 3, p = tid & 7;
        float sum = 0.0f;
        #pragma unroll
        for (int j = 0; j < 8; j++) { float x = ys[r * 64 + p * 8 + j]; sum += x * x; }
        sum += __shfl_xor_sync(~0u, sum, 1);
        sum += __shfl_xor_sync(~0u, sum, 2);
        sum += __shfl_xor_sync(~0u, sum, 4);
        if (p == 0) rs[r] = rsqrtf(sum * (1.0f / 64.0f) + 1e-6f);
    }
    __syncthreads();
    for (int i = tid; i < 2048; i += 256)
        ys[i] = ys[i] * rs[i >> 6] * nws[i & 63];
    __syncthreads();

    const int tn = tid & 31;
    const int tm = tid >> 5;
    float acc[4][4];
    #pragma unroll
    for (int i = 0; i < 4; i++)
        #pragma unroll
        for (int j = 0; j < 4; j++) acc[i][j] = 0.0f;

    #pragma unroll 8
    for (int vv = 0; vv < 64; vv++) {
        float b0 = wos[vv * 128 + tn];
        float b1 = wos[vv * 128 + tn + 32];
        float b2 = wos[vv * 128 + tn + 64];
        float b3 = wos[vv * 128 + tn + 96];
        #pragma unroll
        for (int i = 0; i < 4; i++) {
            float a = ys[(tm * 4 + i) * 64 + vv];
            acc[i][0] += a * b0; acc[i][1] += a * b1;
            acc[i][2] += a * b2; acc[i][3] += a * b3;
        }
    }
    #pragma unroll
    for (int i = 0; i < 4; i++) {
        size_t row = (size_t)(m0 + tm * 4 + i) * 2048 + n0 + tn;
        #pragma unroll
        for (int j = 0; j < 4; j++) out[row + 32 * j] = acc[i][j];
    }
}

// =====================================================================
extern "C" void kernel_launch(void* const* d_in, const int* in_sizes, int n_in,
                              void* d_out, int out_size)
{
    const float* x      = (const float*)d_in[0];
    const float* Wk     = (const float*)d_in[1];
    const float* Wv     = (const float*)d_in[2];
    const float* Wq     = (const float*)d_in[3];
    const float* Wa_w   = (const float*)d_in[4];
    const float* Wa_b   = (const float*)d_in[5];
    const float* lam    = (const float*)d_in[6];
    const float* norm_w = (const float*)d_in[7];
    const float* Wo     = (const float*)d_in[8];
    float* out = (float*)d_out;

    proj_gemm<<<dim3(128, 4), 256>>>(x, Wk, Wv, Wq, Wa_w);
    prep_kernel<<<1024, 256>>>(Wa_b, lam);
    ghc_kernel<<<1024, 256>>>();
    scan_kernel<<<4, 288>>>();
    out_gemm<<<dim3(16, 256), 256>>>(norm_w, Wo, out);
}